// round 6
// baseline (speedup 1.0000x reference)
#include <cuda_runtime.h>
#include <cuda_fp16.h>
#include <math.h>
#include <stdint.h>

#define BB 2
#define TT 2048
#define DD 2048
#define HH 16
#define HKK 4
#define HDD 128
#define REP 4
#define ROWS (BB*TT)   // 4096
#define NQKV 3072      // q(2048) | k(512) | v(512)

// tcgen05 availability in THIS compilation pass (arch-specific target only)
#if defined(__CUDA_ARCH__) && (__CUDA_ARCH__ >= 1000) && \
    (defined(__CUDA_ARCH_SPECIFIC__) || defined(__CUDA_ARCH_FAMILY_SPECIFIC__) || \
     defined(__CUDA_ARCH_FEAT_SM103_ALL) || defined(__CUDA_ARCH_FEAT_SM100_ALL))
#define TC5 1
#else
#define TC5 0
#endif

// ---------------- scratch (no cudaMalloc allowed) ----------------
__device__ __align__(256) __half g_xh   [(size_t)ROWS*DD];     // 16MB
__device__ __align__(256) __half g_qkvh [(size_t)ROWS*NQKV];   // 24MB
__device__ __align__(256) __half g_atth [(size_t)ROWS*HH*HDD]; // 16MB
__device__ __align__(256) __half g_wqkvT[(size_t)NQKV*DD];     // 12MB  [N][K]
__device__ __align__(256) __half g_woT  [(size_t)DD*DD];       // 8MB   [N][K]

// ---------------- common primitives ----------------
__device__ __forceinline__ void mma_f16(float* d, const uint32_t* a, const uint32_t* b) {
    asm volatile(
        "mma.sync.aligned.m16n8k16.row.col.f32.f16.f16.f32 "
        "{%0,%1,%2,%3}, {%4,%5,%6,%7}, {%8,%9}, {%0,%1,%2,%3};\n"
        : "+f"(d[0]), "+f"(d[1]), "+f"(d[2]), "+f"(d[3])
        : "r"(a[0]), "r"(a[1]), "r"(a[2]), "r"(a[3]), "r"(b[0]), "r"(b[1]));
}
__device__ __forceinline__ void ldmatrix_x4_trans(uint32_t* r, uint32_t saddr) {
    asm volatile(
        "ldmatrix.sync.aligned.m8n8.x4.trans.shared.b16 {%0,%1,%2,%3}, [%4];"
        : "=r"(r[0]), "=r"(r[1]), "=r"(r[2]), "=r"(r[3]) : "r"(saddr));
}
__device__ __forceinline__ void cp16(uint32_t saddr, const void* g) {
    asm volatile("cp.async.cg.shared.global [%0], [%1], 16;\n" :: "r"(saddr), "l"(g));
}
__device__ __forceinline__ uint32_t packh2(float a, float b) {
    __half2 h = __floats2half2_rn(a, b);
    return *reinterpret_cast<uint32_t*>(&h);
}
__device__ __forceinline__ void mbar_init(uint32_t a, uint32_t cnt) {
    asm volatile("mbarrier.init.shared.b64 [%0], %1;" :: "r"(a), "r"(cnt) : "memory");
}
__device__ __forceinline__ void mbar_arrive(uint32_t a) {
    asm volatile("mbarrier.arrive.shared.b64 _, [%0];" :: "r"(a) : "memory");
}
__device__ __forceinline__ void mbar_wait(uint32_t a, uint32_t parity) {
    asm volatile(
        "{\n\t.reg .pred P;\n"
        "W_%=:\n\t"
        "mbarrier.try_wait.parity.acquire.cta.shared::cta.b64 P, [%0], %1, 0x989680;\n\t"
        "@P bra.uni D_%=;\n\t"
        "bra.uni W_%=;\n"
        "D_%=:\n\t}"
        :: "r"(a), "r"(parity) : "memory");
}
__device__ __forceinline__ void fence_proxy_async_cta() {
    asm volatile("fence.proxy.async.shared::cta;" ::: "memory");
}

#if TC5
// ---- tcgen05 primitives (arch-specific pass only) ----
__device__ __forceinline__ void tmem_alloc(uint32_t smem_slot, uint32_t ncols) {
    asm volatile("tcgen05.alloc.cta_group::1.sync.aligned.shared::cta.b32 [%0], %1;"
                 :: "r"(smem_slot), "r"(ncols) : "memory");
}
__device__ __forceinline__ void tmem_dealloc(uint32_t tmem, uint32_t ncols) {
    asm volatile("tcgen05.dealloc.cta_group::1.sync.aligned.b32 %0, %1;" :: "r"(tmem), "r"(ncols));
}
__device__ __forceinline__ void tmem_relinquish() {
    asm volatile("tcgen05.relinquish_alloc_permit.cta_group::1.sync.aligned;");
}
__device__ __forceinline__ void tc5_commit(uint32_t mbar) {
    asm volatile("tcgen05.commit.cta_group::1.mbarrier::arrive::one.shared::cluster.b64 [%0];"
                 :: "r"(mbar) : "memory");
}
__device__ __forceinline__ void tc5_fence_after() {
    asm volatile("tcgen05.fence::after_thread_sync;" ::: "memory");
}
__device__ __forceinline__ void tc5_mma_f16(uint32_t d_tmem, uint64_t a_desc, uint64_t b_desc,
                                            uint32_t idesc, uint32_t acc) {
    asm volatile(
        "{\n\t.reg .pred p;\n\t"
        "setp.ne.u32 p, %5, 0;\n\t"
        "tcgen05.mma.cta_group::1.kind::f16 [%0], %1, %2, %3, {%4,%4,%4,%4}, p;\n\t}"
        :: "r"(d_tmem), "l"(a_desc), "l"(b_desc), "r"(idesc), "r"(0u), "r"(acc)
        : "memory");
}
__device__ __forceinline__ void tc5_ld_x32(uint32_t* r, uint32_t tmem) {
    asm volatile(
        "tcgen05.ld.sync.aligned.32x32b.x32.b32 "
        "{%0, %1, %2, %3, %4, %5, %6, %7, "
        " %8, %9, %10, %11, %12, %13, %14, %15, "
        " %16, %17, %18, %19, %20, %21, %22, %23, "
        " %24, %25, %26, %27, %28, %29, %30, %31}, [%32];"
        : "=r"(r[0]),  "=r"(r[1]),  "=r"(r[2]),  "=r"(r[3]),
          "=r"(r[4]),  "=r"(r[5]),  "=r"(r[6]),  "=r"(r[7]),
          "=r"(r[8]),  "=r"(r[9]),  "=r"(r[10]), "=r"(r[11]),
          "=r"(r[12]), "=r"(r[13]), "=r"(r[14]), "=r"(r[15]),
          "=r"(r[16]), "=r"(r[17]), "=r"(r[18]), "=r"(r[19]),
          "=r"(r[20]), "=r"(r[21]), "=r"(r[22]), "=r"(r[23]),
          "=r"(r[24]), "=r"(r[25]), "=r"(r[26]), "=r"(r[27]),
          "=r"(r[28]), "=r"(r[29]), "=r"(r[30]), "=r"(r[31])
        : "r"(tmem));
}
__device__ __forceinline__ void tc5_wait_ld() {
    asm volatile("tcgen05.wait::ld.sync.aligned;" ::: "memory");
}
// SW128 K-major descriptor: LBO=1, SBO=64, version=1, layout=SW128
#define SMEM_DESC_BASE ((2ull<<61) | (1ull<<46) | (64ull<<32) | (1ull<<16))
__device__ __forceinline__ uint64_t mkdesc(uint32_t addr) {
    return SMEM_DESC_BASE | ((uint64_t)(addr >> 4) & 0x3FFFull);
}
#endif

// ---------------- prepasses ----------------
__global__ void f32_to_h(const float* __restrict__ in, __half* __restrict__ out, int n4)
{
    int i = blockIdx.x * blockDim.x + threadIdx.x;
    if (i >= n4) return;
    float4 v = reinterpret_cast<const float4*>(in)[i];
    uint2 o;
    o.x = packh2(v.x, v.y);
    o.y = packh2(v.z, v.w);
    reinterpret_cast<uint2*>(out)[i] = o;
}

// out[N][K] (half) = in[K][N] (float)
__global__ void transpose_h(const float* __restrict__ in, __half* __restrict__ out,
                            int R, int C)
{
    __shared__ float t[32][33];
    int c0 = blockIdx.x * 32, r0 = blockIdx.y * 32;
    #pragma unroll
    for (int i = 0; i < 32; i += 8)
        t[threadIdx.y + i][threadIdx.x] =
            in[(size_t)(r0 + threadIdx.y + i) * C + c0 + threadIdx.x];
    __syncthreads();
    #pragma unroll
    for (int i = 0; i < 32; i += 8)
        out[(size_t)(c0 + threadIdx.y + i) * R + r0 + threadIdx.x] =
            __float2half_rn(t[threadIdx.x][threadIdx.y + i]);
}

// ---------------- RoPE (interleaved pairs) on half ----------------
__global__ void rope_h(__half* __restrict__ x,
                       const float* __restrict__ cs, const float* __restrict__ sn,
                       int nh, int row_stride, int total, float scale)
{
    int idx = blockIdx.x * blockDim.x + threadIdx.x;
    if (idx >= total) return;
    int i    = idx % (HDD / 2);
    int rest = idx / (HDD / 2);
    int h    = rest % nh;
    int row  = rest / nh;
    int t    = row % TT;
    float c = cs[t * (HDD / 2) + i];
    float s = sn[t * (HDD / 2) + i];
    __half2* p = reinterpret_cast<__half2*>(x + (size_t)row * row_stride + h * HDD) + i;
    float2 v = __half22float2(*p);
    *p = __floats2half2_rn((v.x * c - v.y * s) * scale, (v.x * s + v.y * c) * scale);
}

// ---------------------------------------------------------------------------
// fp16 GEMM: C[M,N] = A[M,K] @ W  (Bt = W^T as [N][K] half, K-major)
// CTA 128x256.  TC5: tcgen05 kind::f16, K-chunk 64, 4-stage mbarrier pipeline.
//               FB : mma.sync m16n8k16, 8 warps, 64x64 warp tile, 3-stage cp.async.
// ---------------------------------------------------------------------------
#define GBM 128
#define GBN 256
#define GKC 64
// TC5 layout
#define TA_B (GBM*128)                 // 16 KB (128 rows x 128B = 64 halves)
#define TB_B (GBN*128)                 // 32 KB
#define TSTG (TA_B + TB_B)             // 48 KB
#define TC5_SMEM (4*TSTG + 2048)       // 198656
#define TIDESC ((1u<<4) | (16u<<17) | (8u<<24))   // f32 acc, f16xf16, N=128, M=128
// FB layout
#define HSTR 72
#define A_H (GBM*HSTR)
#define B_H (GBN*HSTR)
#define STG_B ((A_H + B_H) * 2)        // 55296
#define FB_SMEM (3 * STG_B)            // 165888
#define GEMM_SMEM_MAX (TC5_SMEM > FB_SMEM ? TC5_SMEM : FB_SMEM)

__global__ void __launch_bounds__(256, 1) gemm_h(
    int M, int N, int K,
    const __half* __restrict__ A, const __half* __restrict__ Bt,
    void* __restrict__ Cv, int half_out)
{
#if TC5
    extern __shared__ char smem[];
    const uint32_t sb   = (uint32_t)__cvta_generic_to_shared(smem);
    const uint32_t data = (sb + 1023u) & ~1023u;
    char* smem_data = smem + (data - sb);
    const uint32_t mb = data + 4 * TSTG;

    const int tid  = threadIdx.x;
    const int lane = tid & 31;
    const int wid  = tid >> 5;
    const int rowBase = blockIdx.y * GBM;
    const int colBase = blockIdx.x * GBN;
    const int nk = K / GKC;

    const uint32_t tmem_slot = mb;
    const uint32_t doneb = mb + 16 + 4 * 16;

    if (tid == 0) {
        #pragma unroll
        for (int s = 0; s < 4; s++) {
            mbar_init(mb + 16 + (uint32_t)s * 16, 1);   // full
            mbar_init(mb + 24 + (uint32_t)s * 16, 1);   // empty
        }
        mbar_init(doneb, 1);
    }
    if (wid == 0) tmem_alloc(tmem_slot, 256);
    __syncthreads();
    uint32_t tmem;
    asm volatile("ld.shared.b32 %0, [%1];" : "=r"(tmem) : "r"(tmem_slot));
    if (wid == 0) tmem_relinquish();

    if (wid >= 1) {
        // producers: LDG -> swizzled STS (data already fp16)
        const int ptid = tid - 32;           // 0..223
        int stage = 0, phase = 1;
        for (int ch = 0; ch < nk; ch++) {
            mbar_wait(mb + 24 + (uint32_t)stage * 16, (uint32_t)phase);
            const __half* Ag = A  + (size_t)rowBase * K + ch * GKC;
            const __half* Bg = Bt + (size_t)colBase * K + ch * GKC;
            char* sA = smem_data + (size_t)stage * TSTG;
            char* sB = sA + TA_B;
            for (int i = ptid; i < (GBM + GBN) * 8; i += 224) {
                if (i < GBM * 8) {
                    int r = i >> 3, c = i & 7;
                    uint4 v = *reinterpret_cast<const uint4*>(Ag + (size_t)r * K + c * 8);
                    uint32_t off = (uint32_t)(r * 128 + c * 16);
                    off ^= (off >> 3) & 0x70u;
                    *reinterpret_cast<uint4*>(sA + off) = v;
                } else {
                    int j = i - GBM * 8;
                    int r = j >> 3, c = j & 7;
                    uint4 v = *reinterpret_cast<const uint4*>(Bg + (size_t)r * K + c * 8);
                    uint32_t off = (uint32_t)(r * 128 + c * 16);
                    off ^= (off >> 3) & 0x70u;
                    *reinterpret_cast<uint4*>(sB + off) = v;
                }
            }
            fence_proxy_async_cta();
            asm volatile("bar.sync 1, 224;" ::: "memory");
            if (tid == 32) mbar_arrive(mb + 16 + (uint32_t)stage * 16);
            if (++stage == 4) { stage = 0; phase ^= 1; }
        }
    } else if (tid == 0) {
        // MMA issuer: 4 x (K=16) steps per chunk, 2 N-halves
        int stage = 0, phase = 0;
        for (int ch = 0; ch < nk; ch++) {
            mbar_wait(mb + 16 + (uint32_t)stage * 16, (uint32_t)phase);
            uint32_t a_addr = data + (uint32_t)stage * TSTG;
            uint32_t b_addr = a_addr + TA_B;
            uint64_t ad = mkdesc(a_addr);
            #pragma unroll
            for (int h2 = 0; h2 < 2; h2++) {
                uint64_t bd = mkdesc(b_addr + (uint32_t)h2 * (128u * 128u));
                #pragma unroll
                for (int ks = 0; ks < 4; ks++)
                    tc5_mma_f16(tmem + h2 * 128, ad + ks * 2, bd + ks * 2, TIDESC,
                                (ch == 0 && ks == 0) ? 0u : 1u);
            }
            tc5_commit(mb + 24 + (uint32_t)stage * 16);
            if (++stage == 4) { stage = 0; phase ^= 1; }
        }
        tc5_commit(doneb);
    }

    mbar_wait(doneb, 0);
    tc5_fence_after();
    if (tid < 128) {
        int row = rowBase + wid * 32 + lane;
        for (int cb = 0; cb < GBN; cb += 32) {
            uint32_t d[32];
            tc5_ld_x32(d, tmem + cb);
            tc5_wait_ld();
            if (half_out) {
                __half* C = (__half*)Cv;
                #pragma unroll
                for (int j = 0; j < 16; j++)
                    *reinterpret_cast<uint32_t*>(C + (size_t)row * N + colBase + cb + j * 2) =
                        packh2(__uint_as_float(d[2*j]), __uint_as_float(d[2*j+1]));
            } else {
                float* C = (float*)Cv;
                #pragma unroll
                for (int j = 0; j < 8; j++) {
                    float4 v;
                    v.x = __uint_as_float(d[4*j+0]);
                    v.y = __uint_as_float(d[4*j+1]);
                    v.z = __uint_as_float(d[4*j+2]);
                    v.w = __uint_as_float(d[4*j+3]);
                    *reinterpret_cast<float4*>(C + (size_t)row * N + colBase + cb + 4 * j) = v;
                }
            }
        }
    }
    __syncthreads();
    if (wid == 0) tmem_dealloc(tmem, 256);

#else   // ------------------- mma.sync fallback (proven R5 kernel) -------------------
    extern __shared__ __half sh[];
    const uint32_t smem_base = (uint32_t)__cvta_generic_to_shared(sh);
    const uint32_t* shw = reinterpret_cast<const uint32_t*>(sh);

    const int tid  = threadIdx.x;
    const int lane = tid & 31;
    const int wid  = tid >> 5;
    const int wm   = wid >> 2;
    const int wn   = wid & 3;
    const int rowBase = blockIdx.y * GBM;
    const int colBase = blockIdx.x * GBN;
    const int nk = K / GKC;

    float acc[4][8][4];
    #pragma unroll
    for (int mt = 0; mt < 4; mt++)
        #pragma unroll
        for (int nt = 0; nt < 8; nt++)
            #pragma unroll
            for (int j = 0; j < 4; j++) acc[mt][nt][j] = 0.0f;

    auto issue = [&](int s) {
        int k0 = s * GKC;
        uint32_t sA = smem_base + (uint32_t)((s % 3) * STG_B);
        uint32_t sB = sA + (uint32_t)(A_H * 2);
        #pragma unroll
        for (int i = 0; i < 4; i++) {
            int idx = tid + i * 256;
            int r = idx >> 3, c = idx & 7;
            cp16(sA + (uint32_t)(r * HSTR + c * 8) * 2u,
                 A + (size_t)(rowBase + r) * K + k0 + c * 8);
        }
        #pragma unroll
        for (int i = 0; i < 8; i++) {
            int idx = tid + i * 256;
            int r = idx >> 3, c = idx & 7;
            cp16(sB + (uint32_t)(r * HSTR + c * 8) * 2u,
                 Bt + (size_t)(colBase + r) * K + k0 + c * 8);
        }
        asm volatile("cp.async.commit_group;\n" ::: "memory");
    };

    issue(0);
    issue(1);

    const int c4 = lane & 3;
    const int g4 = lane >> 2;

    for (int s = 0; s < nk; s++) {
        asm volatile("cp.async.wait_group 1;\n" ::: "memory");
        __syncthreads();
        if (s + 2 < nk) issue(s + 2);

        const uint32_t* Aw = shw + (s % 3) * (STG_B / 4);
        const uint32_t* Bw = Aw + A_H / 2;
        const int WSTR = HSTR / 2;

        #pragma unroll
        for (int k16 = 0; k16 < 4; k16++) {
            const int kw = k16 * 8;
            uint32_t a[4][4], b[8][2];
            #pragma unroll
            for (int mt = 0; mt < 4; mt++) {
                int r = wm * 64 + mt * 16 + g4;
                a[mt][0] = Aw[r * WSTR + kw + c4];
                a[mt][1] = Aw[(r + 8) * WSTR + kw + c4];
                a[mt][2] = Aw[r * WSTR + kw + 4 + c4];
                a[mt][3] = Aw[(r + 8) * WSTR + kw + 4 + c4];
            }
            #pragma unroll
            for (int nt = 0; nt < 8; nt++) {
                int n = wn * 64 + nt * 8 + g4;
                b[nt][0] = Bw[n * WSTR + kw + c4];
                b[nt][1] = Bw[n * WSTR + kw + 4 + c4];
            }
            #pragma unroll
            for (int mt = 0; mt < 4; mt++)
                #pragma unroll
                for (int nt = 0; nt < 8; nt++)
                    mma_f16(acc[mt][nt], a[mt], b[nt]);
        }
        __syncthreads();
    }

    if (half_out) {
        __half* C = (__half*)Cv;
        #pragma unroll
        for (int mt = 0; mt < 4; mt++) {
            int r0 = rowBase + wm * 64 + mt * 16 + g4;
            #pragma unroll
            for (int nt = 0; nt < 8; nt++) {
                int c0 = colBase + wn * 64 + nt * 8 + 2 * c4;
                *reinterpret_cast<__half2*>(C + (size_t)r0 * N + c0) =
                    __floats2half2_rn(acc[mt][nt][0], acc[mt][nt][1]);
                *reinterpret_cast<__half2*>(C + (size_t)(r0 + 8) * N + c0) =
                    __floats2half2_rn(acc[mt][nt][2], acc[mt][nt][3]);
            }
        }
    } else {
        float* C = (float*)Cv;
        #pragma unroll
        for (int mt = 0; mt < 4; mt++) {
            int r0 = rowBase + wm * 64 + mt * 16 + g4;
            #pragma unroll
            for (int nt = 0; nt < 8; nt++) {
                int c0 = colBase + wn * 64 + nt * 8 + 2 * c4;
                *reinterpret_cast<float2*>(C + (size_t)r0 * N + c0) =
                    make_float2(acc[mt][nt][0], acc[mt][nt][1]);
                *reinterpret_cast<float2*>(C + (size_t)(r0 + 8) * N + c0) =
                    make_float2(acc[mt][nt][2], acc[mt][nt][3]);
            }
        }
    }
#endif
}

// ---------------------------------------------------------------------------
// fp16 flash attention, causal. BR=128, BC=64, 8 warps; warp owns 16 q-rows.
// P stays in registers; V via ldmatrix.trans; K/V double-buffered via cp.async.
// qkv layout: row stride 3072 halves; q = h*128, k = 2048+hk*128, v = 2560+hk*128.
// ---------------------------------------------------------------------------
#define FSTR 136
#define FWSTR 68
#define Q_H (128*FSTR)
#define KV_STG (64*FSTR)                        // halves per K (or V) stage
#define FLASH_SMEM ((Q_H + 4*KV_STG) * 2)       // 104448

__global__ void __launch_bounds__(256, 1) flash_h(
    const __half* __restrict__ qkv, __half* __restrict__ att)
{
    extern __shared__ __half sh[];
    __half* Qs = sh;
    const uint32_t smem_base = (uint32_t)__cvta_generic_to_shared(sh);
    const uint32_t* Qw = reinterpret_cast<const uint32_t*>(Qs);

    const int tid  = threadIdx.x;
    const int lane = tid & 31;
    const int wid  = tid >> 5;
    const int bx = gridDim.x - 1 - blockIdx.x;   // heavy tiles first
    const int h = blockIdx.y, b = blockIdx.z;
    const int hk = h / REP;
    const int qrow0 = bx * 128;
    const int c4 = lane & 3;
    const int g4 = lane >> 2;

    // Q load (row stride 3072)
    {
        const __half* qg = qkv + (size_t)(b * TT + qrow0) * NQKV + h * HDD;
        #pragma unroll
        for (int i = 0; i < 8; i++) {
            int idx = tid + i * 256;
            int r = idx >> 4, c = idx & 15;
            *reinterpret_cast<uint4*>(Qs + r * FSTR + c * 8) =
                *reinterpret_cast<const uint4*>(qg + (size_t)r * NQKV + c * 8);
        }
    }
    __syncthreads();

    uint32_t qa[8][4];
    {
        const int r = wid * 16 + g4;
        #pragma unroll
        for (int ks = 0; ks < 8; ks++) {
            int w = ks * 8 + c4;
            qa[ks][0] = Qw[r * FWSTR + w];
            qa[ks][1] = Qw[(r + 8) * FWSTR + w];
            qa[ks][2] = Qw[r * FWSTR + w + 4];
            qa[ks][3] = Qw[(r + 8) * FWSTR + w + 4];
        }
    }

    // cp.async K/V stage loader
    auto issue_kv = [&](int kt, int stg) {
        const __half* kg = qkv + (size_t)(b * TT + kt * 64) * NQKV + 2048 + hk * HDD;
        uint32_t ks_u = smem_base + (uint32_t)(Q_H + stg * 2 * KV_STG) * 2u;
        uint32_t vs_u = ks_u + (uint32_t)KV_STG * 2u;
        #pragma unroll
        for (int i = 0; i < 8; i++) {
            int idx = tid + i * 256;
            int r = (idx >> 4) & 63, c = idx & 15;
            if (idx < 1024)
                cp16(ks_u + (uint32_t)(r * FSTR + c * 8) * 2u,
                     kg + (size_t)r * NQKV + c * 8);
            else
                cp16(vs_u + (uint32_t)(r * FSTR + c * 8) * 2u,
                     kg + 512 + (size_t)r * NQKV + c * 8);
        }
        asm volatile("cp.async.commit_group;\n" ::: "memory");
    };

    float o[16][4];
    #pragma unroll
    for (int nt = 0; nt < 16; nt++)
        #pragma unroll
        for (int j = 0; j < 4; j++) o[nt][j] = 0.0f;

    float m0 = -INFINITY, m1 = -INFINITY, l0 = 0.0f, l1 = 0.0f;
    const int r0g = qrow0 + wid * 16 + g4;
    const int r1g = r0g + 8;

    const int ntile = 2 * bx + 2;
    issue_kv(0, 0);

    for (int kt = 0; kt < ntile; kt++) {
        __syncthreads();   // previous compute done: stage (kt+1)&1 reusable
        if (kt + 1 < ntile) {
            issue_kv(kt + 1, (kt + 1) & 1);
            asm volatile("cp.async.wait_group 1;\n" ::: "memory");
        } else {
            asm volatile("cp.async.wait_group 0;\n" ::: "memory");
        }
        __syncthreads();

        const uint32_t* Kw = reinterpret_cast<const uint32_t*>(sh + Q_H + (kt & 1) * 2 * KV_STG);
        const uint32_t vs_base = smem_base + (uint32_t)(Q_H + (kt & 1) * 2 * KV_STG + KV_STG) * 2u;

        // S = Q K^T  (16 x 64 per warp)
        float s[8][4];
        #pragma unroll
        for (int nt = 0; nt < 8; nt++)
            #pragma unroll
            for (int j = 0; j < 4; j++) s[nt][j] = 0.0f;

        #pragma unroll
        for (int ks = 0; ks < 8; ks++) {
            #pragma unroll
            for (int nt = 0; nt < 8; nt++) {
                uint32_t bb[2];
                int n = nt * 8 + g4;
                int w = ks * 8 + c4;
                bb[0] = Kw[n * FWSTR + w];
                bb[1] = Kw[n * FWSTR + w + 4];
                mma_f16(s[nt], qa[ks], bb);
            }
        }

        if (kt >= 2 * bx) {
            #pragma unroll
            for (int nt = 0; nt < 8; nt++) {
                int c0 = kt * 64 + nt * 8 + 2 * c4;
                if (c0     > r0g) s[nt][0] = -INFINITY;
                if (c0 + 1 > r0g) s[nt][1] = -INFINITY;
                if (c0     > r1g) s[nt][2] = -INFINITY;
                if (c0 + 1 > r1g) s[nt][3] = -INFINITY;
            }
        }

        float mx0 = -INFINITY, mx1 = -INFINITY;
        #pragma unroll
        for (int nt = 0; nt < 8; nt++) {
            mx0 = fmaxf(mx0, fmaxf(s[nt][0], s[nt][1]));
            mx1 = fmaxf(mx1, fmaxf(s[nt][2], s[nt][3]));
        }
        mx0 = fmaxf(mx0, __shfl_xor_sync(0xffffffffu, mx0, 1));
        mx0 = fmaxf(mx0, __shfl_xor_sync(0xffffffffu, mx0, 2));
        mx1 = fmaxf(mx1, __shfl_xor_sync(0xffffffffu, mx1, 1));
        mx1 = fmaxf(mx1, __shfl_xor_sync(0xffffffffu, mx1, 2));

        float nm0 = fmaxf(m0, mx0), nm1 = fmaxf(m1, mx1);
        float al0 = __expf(m0 - nm0), al1 = __expf(m1 - nm1);
        m0 = nm0; m1 = nm1;

        uint32_t ph0[8], ph1[8];
        float ps0 = 0.0f, ps1 = 0.0f;
        #pragma unroll
        for (int nt = 0; nt < 8; nt++) {
            ph0[nt] = packh2(__expf(s[nt][0] - nm0), __expf(s[nt][1] - nm0));
            ph1[nt] = packh2(__expf(s[nt][2] - nm1), __expf(s[nt][3] - nm1));
            float2 f0 = __half22float2(*reinterpret_cast<__half2*>(&ph0[nt]));
            float2 f1 = __half22float2(*reinterpret_cast<__half2*>(&ph1[nt]));
            ps0 += f0.x + f0.y;
            ps1 += f1.x + f1.y;
        }
        ps0 += __shfl_xor_sync(0xffffffffu, ps0, 1);
        ps0 += __shfl_xor_sync(0xffffffffu, ps0, 2);
        ps1 += __shfl_xor_sync(0xffffffffu, ps1, 1);
        ps1 += __shfl_xor_sync(0xffffffffu, ps1, 2);
        l0 = l0 * al0 + ps0;
        l1 = l1 * al1 + ps1;

        #pragma unroll
        for (int nt = 0; nt < 16; nt++) {
            o[nt][0] *= al0; o[nt][1] *= al0;
            o[nt][2] *= al1; o[nt][3] *= al1;
        }

        // O += P @ V
        const int lm = lane >> 3;
        const int lr = lane & 7;
        #pragma unroll
        for (int ks2 = 0; ks2 < 4; ks2++) {
            uint32_t pa[4] = { ph0[2*ks2], ph1[2*ks2], ph0[2*ks2+1], ph1[2*ks2+1] };
            #pragma unroll
            for (int nb = 0; nb < 8; nb++) {
                uint32_t vb[4];
                int srow = ks2 * 16 + (lm & 1) * 8 + lr;
                int dcol = nb * 16 + (lm >> 1) * 8;
                ldmatrix_x4_trans(vb, vs_base + (uint32_t)(srow * FSTR + dcol) * 2u);
                mma_f16(o[2*nb],     pa, vb);
                mma_f16(o[2*nb + 1], pa, vb + 2);
            }
        }
    }

    const float inv0 = 1.0f / l0, inv1 = 1.0f / l1;
    #pragma unroll
    for (int nt2 = 0; nt2 < 16; nt2++) {
        int c = h * HDD + nt2 * 8 + 2 * c4;
        size_t base0 = (size_t)(b * TT + r0g) * (HH * HDD) + c;
        size_t base1 = (size_t)(b * TT + r1g) * (HH * HDD) + c;
        *reinterpret_cast<__half2*>(att + base0) =
            __floats2half2_rn(o[nt2][0] * inv0, o[nt2][1] * inv0);
        *reinterpret_cast<__half2*>(att + base1) =
            __floats2half2_rn(o[nt2][2] * inv1, o[nt2][3] * inv1);
    }
}

// ---------------------------------------------------------------------------
extern "C" void kernel_launch(void* const* d_in, const int* in_sizes, int n_in,
                              void* d_out, int out_size)
{
    const float* x  = (const float*)d_in[0];
    const float* fc = (const float*)d_in[1];
    const float* fs = (const float*)d_in[2];
    // d_in[3] = mask — enforced analytically
    const float* wq = (const float*)d_in[4];
    const float* wk = (const float*)d_in[5];
    const float* wv = (const float*)d_in[6];
    const float* wo = (const float*)d_in[7];
    float* out = (float*)d_out;

    __half *xh, *qkvh, *atth, *wqkvT, *woT;
    cudaGetSymbolAddress((void**)&xh,    g_xh);
    cudaGetSymbolAddress((void**)&qkvh,  g_qkvh);
    cudaGetSymbolAddress((void**)&atth,  g_atth);
    cudaGetSymbolAddress((void**)&wqkvT, g_wqkvT);
    cudaGetSymbolAddress((void**)&woT,   g_woT);

    cudaFuncSetAttribute(gemm_h,  cudaFuncAttributeMaxDynamicSharedMemorySize, (int)GEMM_SMEM_MAX);
    cudaFuncSetAttribute(flash_h, cudaFuncAttributeMaxDynamicSharedMemorySize, (int)FLASH_SMEM);

    // 1) fp16 conversions; pack wq|wk|wv transposed into one [3072][2048] operand
    f32_to_h<<<(ROWS*DD/4 + 255)/256, 256>>>(x, xh, ROWS*DD/4);
    transpose_h<<<dim3(DD/32, DD/32), dim3(32, 8)>>>(wq, wqkvT, DD, DD);
    transpose_h<<<dim3(512/32, DD/32), dim3(32, 8)>>>(wk, wqkvT + (size_t)2048 * DD, DD, 512);
    transpose_h<<<dim3(512/32, DD/32), dim3(32, 8)>>>(wv, wqkvT + (size_t)2560 * DD, DD, 512);
    transpose_h<<<dim3(DD/32, DD/32), dim3(32, 8)>>>(wo, woT, DD, DD);

    // 2) fused QKV projection
    gemm_h<<<dim3(NQKV/GBN, ROWS/GBM), 256, GEMM_SMEM_MAX>>>(ROWS, NQKV, DD, xh, wqkvT, qkvh, 1);

    // 3) RoPE (+ fold 1/sqrt(HD) into q)
    {
        int totq = ROWS * HH  * (HDD / 2);
        int totk = ROWS * HKK * (HDD / 2);
        rope_h<<<(totq + 255)/256, 256>>>(qkvh,        fc, fs, HH,  NQKV, totq, 0.08838834764831845f);
        rope_h<<<(totk + 255)/256, 256>>>(qkvh + 2048, fc, fs, HKK, NQKV, totk, 1.0f);
    }

    // 4) fp16 flash attention (double-buffered K/V)
    flash_h<<<dim3(TT/128, HH, BB), 256, FLASH_SMEM>>>(qkvh, atth);

    // 5) output projection (fp32 out)
    gemm_h<<<dim3(DD/GBN, ROWS/GBM), 256, GEMM_SMEM_MAX>>>(ROWS, DD, HH*HDD, atth, woT, out, 0);
}

// round 7
// speedup vs baseline: 1.5066x; 1.5066x over previous
#include <cuda_runtime.h>
#include <cuda_fp16.h>
#include <math.h>
#include <stdint.h>

#define BB 2
#define TT 2048
#define DD 2048
#define HH 16
#define HKK 4
#define HDD 128
#define REP 4
#define ROWS (BB*TT)   // 4096

// ---------------- scratch (no cudaMalloc allowed) ----------------
__device__ __align__(256) __half g_xh  [(size_t)ROWS*DD];      // 16MB
__device__ __align__(256) __half g_qh  [(size_t)ROWS*HH*HDD];  // 16MB
__device__ __align__(256) __half g_kvh [(size_t)ROWS*1024];    // 8MB  (k 0-511 | v 512-1023)
__device__ __align__(256) __half g_atth[(size_t)ROWS*HH*HDD];  // 16MB
__device__ __align__(256) __half g_wqT [(size_t)DD*DD];        // 8MB  [N][K]
__device__ __align__(256) __half g_wkvT[(size_t)1024*DD];      // 4MB
__device__ __align__(256) __half g_woT [(size_t)DD*DD];        // 8MB

// ---------------- primitives ----------------
__device__ __forceinline__ void mma_f16(float* d, const uint32_t* a, const uint32_t* b) {
    asm volatile(
        "mma.sync.aligned.m16n8k16.row.col.f32.f16.f16.f32 "
        "{%0,%1,%2,%3}, {%4,%5,%6,%7}, {%8,%9}, {%0,%1,%2,%3};\n"
        : "+f"(d[0]), "+f"(d[1]), "+f"(d[2]), "+f"(d[3])
        : "r"(a[0]), "r"(a[1]), "r"(a[2]), "r"(a[3]), "r"(b[0]), "r"(b[1]));
}
__device__ __forceinline__ void ldmatrix_x4_trans(uint32_t* r, uint32_t saddr) {
    asm volatile(
        "ldmatrix.sync.aligned.m8n8.x4.trans.shared.b16 {%0,%1,%2,%3}, [%4];"
        : "=r"(r[0]), "=r"(r[1]), "=r"(r[2]), "=r"(r[3]) : "r"(saddr));
}
__device__ __forceinline__ void cp16(uint32_t saddr, const void* g) {
    asm volatile("cp.async.cg.shared.global [%0], [%1], 16;\n" :: "r"(saddr), "l"(g));
}
__device__ __forceinline__ uint32_t packh2(float a, float b) {
    __half2 h = __floats2half2_rn(a, b);
    return *reinterpret_cast<uint32_t*>(&h);
}

// ---------------- prepasses ----------------
__global__ void f32_to_h(const float* __restrict__ in, __half* __restrict__ out, int n4)
{
    int i = blockIdx.x * blockDim.x + threadIdx.x;
    if (i >= n4) return;
    float4 v = reinterpret_cast<const float4*>(in)[i];
    uint2 o;
    o.x = packh2(v.x, v.y);
    o.y = packh2(v.z, v.w);
    reinterpret_cast<uint2*>(out)[i] = o;
}

// out[N][K] (half) = in[K][N] (float)
__global__ void transpose_h(const float* __restrict__ in, __half* __restrict__ out,
                            int R, int C)
{
    __shared__ float t[32][33];
    int c0 = blockIdx.x * 32, r0 = blockIdx.y * 32;
    #pragma unroll
    for (int i = 0; i < 32; i += 8)
        t[threadIdx.y + i][threadIdx.x] =
            in[(size_t)(r0 + threadIdx.y + i) * C + c0 + threadIdx.x];
    __syncthreads();
    #pragma unroll
    for (int i = 0; i < 32; i += 8)
        out[(size_t)(c0 + threadIdx.y + i) * R + r0 + threadIdx.x] =
            __float2half_rn(t[threadIdx.x][threadIdx.y + i]);
}

// ---------------- RoPE (interleaved pairs) on half ----------------
__global__ void rope_h(__half* __restrict__ x,
                       const float* __restrict__ cs, const float* __restrict__ sn,
                       int nh, int row_stride, int total, float scale)
{
    int idx = blockIdx.x * blockDim.x + threadIdx.x;
    if (idx >= total) return;
    int i    = idx % (HDD / 2);
    int rest = idx / (HDD / 2);
    int h    = rest % nh;
    int row  = rest / nh;
    int t    = row % TT;
    float c = cs[t * (HDD / 2) + i];
    float s = sn[t * (HDD / 2) + i];
    __half2* p = reinterpret_cast<__half2*>(x + (size_t)row * row_stride + h * HDD) + i;
    float2 v = __half22float2(*p);
    *p = __floats2half2_rn((v.x * c - v.y * s) * scale, (v.x * s + v.y * c) * scale);
}

// ---------------------------------------------------------------------------
// fp16 GEMM: C[M,N] = A[M,K] @ W  (Bt = W^T as [N][K] half, K-major)
// CTA 128x256, BK=64, 3-stage cp.async, 512 threads (16 warps, 4x4 grid),
// warp tile 32x64. smem rows padded to 72 halves -> conflict-free b32 loads.
// ---------------------------------------------------------------------------
#define GBM 128
#define GBN 256
#define GKC 64
#define HSTR 72
#define A_H (GBM*HSTR)
#define B_H (GBN*HSTR)
#define STG_B ((A_H + B_H) * 2)        // 55296 bytes/stage
#define GEMM_SMEM (3 * STG_B)          // 165888

__global__ void __launch_bounds__(512, 1) gemm_h(
    int M, int N, int K,
    const __half* __restrict__ A, const __half* __restrict__ Bt,
    void* __restrict__ Cv, int half_out)
{
    extern __shared__ __half sh[];
    const uint32_t smem_base = (uint32_t)__cvta_generic_to_shared(sh);
    const uint32_t* shw = reinterpret_cast<const uint32_t*>(sh);

    const int tid  = threadIdx.x;
    const int lane = tid & 31;
    const int wid  = tid >> 5;          // 0..15
    const int wm   = wid >> 2;          // 0..3 (row)
    const int wn   = wid & 3;           // 0..3 (col)
    const int rowBase = blockIdx.y * GBM;
    const int colBase = blockIdx.x * GBN;
    const int nk = K / GKC;

    float acc[2][8][4];
    #pragma unroll
    for (int mt = 0; mt < 2; mt++)
        #pragma unroll
        for (int nt = 0; nt < 8; nt++)
            #pragma unroll
            for (int j = 0; j < 4; j++) acc[mt][nt][j] = 0.0f;

    auto issue = [&](int s) {
        int k0 = s * GKC;
        uint32_t sA = smem_base + (uint32_t)((s % 3) * STG_B);
        uint32_t sB = sA + (uint32_t)(A_H * 2);
        #pragma unroll
        for (int i = 0; i < 2; i++) {               // A: 1024 chunks
            int idx = tid + i * 512;
            int r = idx >> 3, c = idx & 7;
            cp16(sA + (uint32_t)(r * HSTR + c * 8) * 2u,
                 A + (size_t)(rowBase + r) * K + k0 + c * 8);
        }
        #pragma unroll
        for (int i = 0; i < 4; i++) {               // B: 2048 chunks
            int idx = tid + i * 512;
            int r = idx >> 3, c = idx & 7;
            cp16(sB + (uint32_t)(r * HSTR + c * 8) * 2u,
                 Bt + (size_t)(colBase + r) * K + k0 + c * 8);
        }
        asm volatile("cp.async.commit_group;\n" ::: "memory");
    };

    issue(0);
    issue(1);

    const int c4 = lane & 3;
    const int g4 = lane >> 2;

    for (int s = 0; s < nk; s++) {
        asm volatile("cp.async.wait_group 1;\n" ::: "memory");
        __syncthreads();
        if (s + 2 < nk) issue(s + 2);

        const uint32_t* Aw = shw + (s % 3) * (STG_B / 4);
        const uint32_t* Bw = Aw + A_H / 2;
        const int WSTR = HSTR / 2;      // 36 words per row

        #pragma unroll
        for (int k16 = 0; k16 < 4; k16++) {
            const int kw = k16 * 8;
            uint32_t a[2][4], b[8][2];
            #pragma unroll
            for (int mt = 0; mt < 2; mt++) {
                int r = wm * 32 + mt * 16 + g4;
                a[mt][0] = Aw[r * WSTR + kw + c4];
                a[mt][1] = Aw[(r + 8) * WSTR + kw + c4];
                a[mt][2] = Aw[r * WSTR + kw + 4 + c4];
                a[mt][3] = Aw[(r + 8) * WSTR + kw + 4 + c4];
            }
            #pragma unroll
            for (int nt = 0; nt < 8; nt++) {
                int n = wn * 64 + nt * 8 + g4;
                b[nt][0] = Bw[n * WSTR + kw + c4];
                b[nt][1] = Bw[n * WSTR + kw + 4 + c4];
            }
            #pragma unroll
            for (int mt = 0; mt < 2; mt++)
                #pragma unroll
                for (int nt = 0; nt < 8; nt++)
                    mma_f16(acc[mt][nt], a[mt], b[nt]);
        }
        __syncthreads();
    }

    if (half_out) {
        __half* C = (__half*)Cv;
        #pragma unroll
        for (int mt = 0; mt < 2; mt++) {
            int r0 = rowBase + wm * 32 + mt * 16 + g4;
            #pragma unroll
            for (int nt = 0; nt < 8; nt++) {
                int c0 = colBase + wn * 64 + nt * 8 + 2 * c4;
                *reinterpret_cast<__half2*>(C + (size_t)r0 * N + c0) =
                    __floats2half2_rn(acc[mt][nt][0], acc[mt][nt][1]);
                *reinterpret_cast<__half2*>(C + (size_t)(r0 + 8) * N + c0) =
                    __floats2half2_rn(acc[mt][nt][2], acc[mt][nt][3]);
            }
        }
    } else {
        float* C = (float*)Cv;
        #pragma unroll
        for (int mt = 0; mt < 2; mt++) {
            int r0 = rowBase + wm * 32 + mt * 16 + g4;
            #pragma unroll
            for (int nt = 0; nt < 8; nt++) {
                int c0 = colBase + wn * 64 + nt * 8 + 2 * c4;
                *reinterpret_cast<float2*>(C + (size_t)r0 * N + c0) =
                    make_float2(acc[mt][nt][0], acc[mt][nt][1]);
                *reinterpret_cast<float2*>(C + (size_t)(r0 + 8) * N + c0) =
                    make_float2(acc[mt][nt][2], acc[mt][nt][3]);
            }
        }
    }
}

// ---------------------------------------------------------------------------
// fp16 flash attention, causal. BR=128, BC=64, 8 warps; warp owns 16 q-rows.
// P in registers; V via ldmatrix.trans.
// K/V double-buffered cp.async, overlaid on dead Q smem -> total smem 69632 B
// (3 CTAs/SM occupancy preserved).
// ---------------------------------------------------------------------------
#define FSTR 136
#define FWSTR 68
#define KVH (64*FSTR)                    // 8704 halves per K (or V) stage
#define FLASH_SMEM (4*KVH*2)             // 69632 bytes (Q overlays stages 0-1)

__global__ void __launch_bounds__(256, 1) flash_h(
    const __half* __restrict__ q, const __half* __restrict__ kv,
    __half* __restrict__ att)
{
    extern __shared__ __half sh[];
    const uint32_t smem_base = (uint32_t)__cvta_generic_to_shared(sh);

    const int tid  = threadIdx.x;
    const int lane = tid & 31;
    const int wid  = tid >> 5;
    const int bx = gridDim.x - 1 - blockIdx.x;   // heavy tiles first
    const int h = blockIdx.y, b = blockIdx.z;
    const int hk = h / REP;
    const int qrow0 = bx * 128;
    const int c4 = lane & 3;
    const int g4 = lane >> 2;

    // Phase 1: Q via smem (overlaps the KV stage region; dead after extraction)
    {
        const __half* qg = q + ((size_t)(b * TT + qrow0) * HH + h) * HDD;
        #pragma unroll
        for (int i = 0; i < 8; i++) {
            int idx = tid + i * 256;
            int r = idx >> 4, c = idx & 15;
            *reinterpret_cast<uint4*>(sh + r * FSTR + c * 8) =
                *reinterpret_cast<const uint4*>(qg + (size_t)r * HH * HDD + c * 8);
        }
    }
    __syncthreads();

    uint32_t qa[8][4];
    {
        const uint32_t* Qw = reinterpret_cast<const uint32_t*>(sh);
        const int r = wid * 16 + g4;
        #pragma unroll
        for (int ks = 0; ks < 8; ks++) {
            int w = ks * 8 + c4;
            qa[ks][0] = Qw[r * FWSTR + w];
            qa[ks][1] = Qw[(r + 8) * FWSTR + w];
            qa[ks][2] = Qw[r * FWSTR + w + 4];
            qa[ks][3] = Qw[(r + 8) * FWSTR + w + 4];
        }
    }
    __syncthreads();   // Q fully consumed; smem free for K/V stages

    auto issue_kv = [&](int kt, int stg) {
        const __half* kg = kv + (size_t)(b * TT + kt * 64) * 1024 + hk * HDD;
        uint32_t ks_u = smem_base + (uint32_t)(stg * 2 * KVH) * 2u;
        uint32_t vs_u = ks_u + (uint32_t)KVH * 2u;
        #pragma unroll
        for (int i = 0; i < 8; i++) {
            int idx = tid + i * 256;
            int r = (idx >> 4) & 63, c = idx & 15;
            if (idx < 1024)
                cp16(ks_u + (uint32_t)(r * FSTR + c * 8) * 2u,
                     kg + (size_t)r * 1024 + c * 8);
            else
                cp16(vs_u + (uint32_t)(r * FSTR + c * 8) * 2u,
                     kg + 512 + (size_t)r * 1024 + c * 8);
        }
        asm volatile("cp.async.commit_group;\n" ::: "memory");
    };

    float o[16][4];
    #pragma unroll
    for (int nt = 0; nt < 16; nt++)
        #pragma unroll
        for (int j = 0; j < 4; j++) o[nt][j] = 0.0f;

    float m0 = -INFINITY, m1 = -INFINITY, l0 = 0.0f, l1 = 0.0f;
    const int r0g = qrow0 + wid * 16 + g4;
    const int r1g = r0g + 8;

    const int ntile = 2 * bx + 2;
    issue_kv(0, 0);

    for (int kt = 0; kt < ntile; kt++) {
        __syncthreads();   // stage (kt+1)&1 readers (iter kt-1) done
        if (kt + 1 < ntile) {
            issue_kv(kt + 1, (kt + 1) & 1);
            asm volatile("cp.async.wait_group 1;\n" ::: "memory");
        } else {
            asm volatile("cp.async.wait_group 0;\n" ::: "memory");
        }
        __syncthreads();

        const uint32_t* Kw = reinterpret_cast<const uint32_t*>(sh + (kt & 1) * 2 * KVH);
        const uint32_t vs_base = smem_base + (uint32_t)((kt & 1) * 2 * KVH + KVH) * 2u;

        // S = Q K^T  (16 x 64 per warp)
        float s[8][4];
        #pragma unroll
        for (int nt = 0; nt < 8; nt++)
            #pragma unroll
            for (int j = 0; j < 4; j++) s[nt][j] = 0.0f;

        #pragma unroll
        for (int ks = 0; ks < 8; ks++) {
            #pragma unroll
            for (int nt = 0; nt < 8; nt++) {
                uint32_t bb[2];
                int n = nt * 8 + g4;
                int w = ks * 8 + c4;
                bb[0] = Kw[n * FWSTR + w];
                bb[1] = Kw[n * FWSTR + w + 4];
                mma_f16(s[nt], qa[ks], bb);
            }
        }

        if (kt >= 2 * bx) {
            #pragma unroll
            for (int nt = 0; nt < 8; nt++) {
                int c0 = kt * 64 + nt * 8 + 2 * c4;
                if (c0     > r0g) s[nt][0] = -INFINITY;
                if (c0 + 1 > r0g) s[nt][1] = -INFINITY;
                if (c0     > r1g) s[nt][2] = -INFINITY;
                if (c0 + 1 > r1g) s[nt][3] = -INFINITY;
            }
        }

        float mx0 = -INFINITY, mx1 = -INFINITY;
        #pragma unroll
        for (int nt = 0; nt < 8; nt++) {
            mx0 = fmaxf(mx0, fmaxf(s[nt][0], s[nt][1]));
            mx1 = fmaxf(mx1, fmaxf(s[nt][2], s[nt][3]));
        }
        mx0 = fmaxf(mx0, __shfl_xor_sync(0xffffffffu, mx0, 1));
        mx0 = fmaxf(mx0, __shfl_xor_sync(0xffffffffu, mx0, 2));
        mx1 = fmaxf(mx1, __shfl_xor_sync(0xffffffffu, mx1, 1));
        mx1 = fmaxf(mx1, __shfl_xor_sync(0xffffffffu, mx1, 2));

        float nm0 = fmaxf(m0, mx0), nm1 = fmaxf(m1, mx1);
        float al0 = __expf(m0 - nm0), al1 = __expf(m1 - nm1);
        m0 = nm0; m1 = nm1;

        uint32_t ph0[8], ph1[8];
        float ps0 = 0.0f, ps1 = 0.0f;
        #pragma unroll
        for (int nt = 0; nt < 8; nt++) {
            ph0[nt] = packh2(__expf(s[nt][0] - nm0), __expf(s[nt][1] - nm0));
            ph1[nt] = packh2(__expf(s[nt][2] - nm1), __expf(s[nt][3] - nm1));
            float2 f0 = __half22float2(*reinterpret_cast<__half2*>(&ph0[nt]));
            float2 f1 = __half22float2(*reinterpret_cast<__half2*>(&ph1[nt]));
            ps0 += f0.x + f0.y;
            ps1 += f1.x + f1.y;
        }
        ps0 += __shfl_xor_sync(0xffffffffu, ps0, 1);
        ps0 += __shfl_xor_sync(0xffffffffu, ps0, 2);
        ps1 += __shfl_xor_sync(0xffffffffu, ps1, 1);
        ps1 += __shfl_xor_sync(0xffffffffu, ps1, 2);
        l0 = l0 * al0 + ps0;
        l1 = l1 * al1 + ps1;

        #pragma unroll
        for (int nt = 0; nt < 16; nt++) {
            o[nt][0] *= al0; o[nt][1] *= al0;
            o[nt][2] *= al1; o[nt][3] *= al1;
        }

        // O += P @ V
        const int lm = lane >> 3;
        const int lr = lane & 7;
        #pragma unroll
        for (int ks2 = 0; ks2 < 4; ks2++) {
            uint32_t pa[4] = { ph0[2*ks2], ph1[2*ks2], ph0[2*ks2+1], ph1[2*ks2+1] };
            #pragma unroll
            for (int nb = 0; nb < 8; nb++) {
                uint32_t vb[4];
                int srow = ks2 * 16 + (lm & 1) * 8 + lr;
                int dcol = nb * 16 + (lm >> 1) * 8;
                ldmatrix_x4_trans(vb, vs_base + (uint32_t)(srow * FSTR + dcol) * 2u);
                mma_f16(o[2*nb],     pa, vb);
                mma_f16(o[2*nb + 1], pa, vb + 2);
            }
        }
    }

    const float inv0 = 1.0f / l0, inv1 = 1.0f / l1;
    #pragma unroll
    for (int nt2 = 0; nt2 < 16; nt2++) {
        int c = h * HDD + nt2 * 8 + 2 * c4;
        size_t base0 = (size_t)(b * TT + r0g) * (HH * HDD) + c;
        size_t base1 = (size_t)(b * TT + r1g) * (HH * HDD) + c;
        *reinterpret_cast<__half2*>(att + base0) =
            __floats2half2_rn(o[nt2][0] * inv0, o[nt2][1] * inv0);
        *reinterpret_cast<__half2*>(att + base1) =
            __floats2half2_rn(o[nt2][2] * inv1, o[nt2][3] * inv1);
    }
}

// ---------------------------------------------------------------------------
extern "C" void kernel_launch(void* const* d_in, const int* in_sizes, int n_in,
                              void* d_out, int out_size)
{
    const float* x  = (const float*)d_in[0];
    const float* fc = (const float*)d_in[1];
    const float* fs = (const float*)d_in[2];
    // d_in[3] = mask — enforced analytically
    const float* wq = (const float*)d_in[4];
    const float* wk = (const float*)d_in[5];
    const float* wv = (const float*)d_in[6];
    const float* wo = (const float*)d_in[7];
    float* out = (float*)d_out;

    __half *xh, *qh, *kvh, *atth, *wqT, *wkvT, *woT;
    cudaGetSymbolAddress((void**)&xh,   g_xh);
    cudaGetSymbolAddress((void**)&qh,   g_qh);
    cudaGetSymbolAddress((void**)&kvh,  g_kvh);
    cudaGetSymbolAddress((void**)&atth, g_atth);
    cudaGetSymbolAddress((void**)&wqT,  g_wqT);
    cudaGetSymbolAddress((void**)&wkvT, g_wkvT);
    cudaGetSymbolAddress((void**)&woT,  g_woT);

    cudaFuncSetAttribute(gemm_h,  cudaFuncAttributeMaxDynamicSharedMemorySize, GEMM_SMEM);
    cudaFuncSetAttribute(flash_h, cudaFuncAttributeMaxDynamicSharedMemorySize, (int)FLASH_SMEM);

    // 1) fp16 conversions
    f32_to_h<<<(ROWS*DD/4 + 255)/256, 256>>>(x, xh, ROWS*DD/4);
    transpose_h<<<dim3(DD/32, DD/32), dim3(32, 8)>>>(wq, wqT, DD, DD);
    transpose_h<<<dim3(512/32, DD/32), dim3(32, 8)>>>(wk, wkvT, DD, 512);
    transpose_h<<<dim3(512/32, DD/32), dim3(32, 8)>>>(wv, wkvT + (size_t)512 * DD, DD, 512);
    transpose_h<<<dim3(DD/32, DD/32), dim3(32, 8)>>>(wo, woT, DD, DD);

    // 2) projections (fp16 in, fp16 out)
    gemm_h<<<dim3(DD/GBN, ROWS/GBM), 512, GEMM_SMEM>>>(ROWS, DD,   DD, xh, wqT,  qh,  1);
    gemm_h<<<dim3(1024/GBN, ROWS/GBM), 512, GEMM_SMEM>>>(ROWS, 1024, DD, xh, wkvT, kvh, 1);

    // 3) RoPE (+ fold 1/sqrt(HD) into q)
    {
        int totq = ROWS * HH  * (HDD / 2);
        int totk = ROWS * HKK * (HDD / 2);
        rope_h<<<(totq + 255)/256, 256>>>(qh,  fc, fs, HH,  HH*HDD, totq, 0.08838834764831845f);
        rope_h<<<(totk + 255)/256, 256>>>(kvh, fc, fs, HKK, 1024,   totk, 1.0f);
    }

    // 4) fp16 flash attention (double-buffered K/V, occupancy-preserving)
    flash_h<<<dim3(TT/128, HH, BB), 256, FLASH_SMEM>>>(qh, kvh, atth);

    // 5) output projection (fp32 out)
    gemm_h<<<dim3(DD/GBN, ROWS/GBM), 512, GEMM_SMEM>>>(ROWS, DD, HH*HDD, atth, woT, out, 0);
}